// round 5
// baseline (speedup 1.0000x reference)
#include <cuda_runtime.h>
#include <math.h>

// Learned optimizer step. Inputs (metadata order):
// 0 grad[N] 1 state0[N] 2 state1[N] 3 loss_cur[1] 4 loss_old[1] 5 iteration[1]
// 6 gradient_param[N] 7 extrapolation[N]
// 8 cw0[20x4] 9 cb0[20] 10 cw1[20x20] 11 cb1[20] 12 cw2[20x20] 13 cb2[20]
// 14 cw3[1x20] 15 cb3[1]
// 16 lw0[30x6] 17 lb0[30] 18 lw1[20x30] 19 lb1[20] 20 lw2[10x20] 21 lb2[10]
// 22 lw3[4x10] 23 lb3[4]
// Output: float32 [N]
//
// This revision is built for PROVABLY ZERO local-memory/stack usage in every
// kernel: no inline asm, no 64-bit packed values (no register-pair alignment
// pressure), no local arrays anywhere. All per-thread state is named float
// scalars; all intermediates of the tiny MLP live in shared memory.

#define RED_BLOCKS 1024
#define RED_THREADS 256
#define MAIN_THREADS 256
#define MAIN_BLOCKS 4096

__device__ float4 g_part[RED_BLOCKS];
__device__ float g_coeff[4];
__device__ float g_inv_gn;
__device__ float g_inv_dn;
__device__ float g_fscale;

// ---------------------------------------------------------------------------
// Kernel A: block partial reductions (sum g^2, sum d^2, sum g*d, max|g|)
// ---------------------------------------------------------------------------
__global__ void reduce_kernel(const float* __restrict__ grad,
                              const float* __restrict__ s0,
                              const float* __restrict__ s1, int n) {
    int n4 = n >> 2;
    float sg2 = 0.f, sd2 = 0.f, sgd = 0.f, amax = 0.f;
    for (int i = blockIdx.x * blockDim.x + threadIdx.x; i < n4;
         i += gridDim.x * blockDim.x) {
        float4 g = ((const float4*)grad)[i];
        float4 a = ((const float4*)s0)[i];
        float4 b = ((const float4*)s1)[i];
        float dx = b.x - a.x, dy = b.y - a.y, dz = b.z - a.z, dw = b.w - a.w;
        sg2 += g.x * g.x + g.y * g.y + g.z * g.z + g.w * g.w;
        sd2 += dx * dx + dy * dy + dz * dz + dw * dw;
        sgd += g.x * dx + g.y * dy + g.z * dz + g.w * dw;
        amax = fmaxf(amax, fmaxf(fmaxf(fabsf(g.x), fabsf(g.y)),
                                 fmaxf(fabsf(g.z), fabsf(g.w))));
    }
    #pragma unroll
    for (int off = 16; off; off >>= 1) {
        sg2 += __shfl_down_sync(0xffffffffu, sg2, off);
        sd2 += __shfl_down_sync(0xffffffffu, sd2, off);
        sgd += __shfl_down_sync(0xffffffffu, sgd, off);
        amax = fmaxf(amax, __shfl_down_sync(0xffffffffu, amax, off));
    }
    __shared__ float4 sh[RED_THREADS / 32];
    int lane = threadIdx.x & 31, w = threadIdx.x >> 5;
    if (!lane) sh[w] = make_float4(sg2, sd2, sgd, amax);
    __syncthreads();
    if (threadIdx.x == 0) {
        float4 v = sh[0];
        #pragma unroll
        for (int i = 1; i < RED_THREADS / 32; i++) {
            float4 q = sh[i];
            v.x += q.x; v.y += q.y; v.z += q.z; v.w = fmaxf(v.w, q.w);
        }
        g_part[blockIdx.x] = v;
    }
}

// ---------------------------------------------------------------------------
// Kernel B: combine partials + tiny coefficient MLP (intermediates in shared)
// ---------------------------------------------------------------------------
__global__ void scalars_kernel(const float* __restrict__ loss_cur,
                               const float* __restrict__ loss_old,
                               const int* __restrict__ iter_p,
                               const float* __restrict__ lw0, const float* __restrict__ lb0,
                               const float* __restrict__ lw1, const float* __restrict__ lb1,
                               const float* __restrict__ lw2, const float* __restrict__ lb2,
                               const float* __restrict__ lw3, const float* __restrict__ lb3) {
    __shared__ float4 sh[8];
    __shared__ float sfeat[6];
    __shared__ float sh0[30];
    __shared__ float sh1[20];
    __shared__ float sh2[10];

    int tid = threadIdx.x;  // 256 threads
    float sg2 = 0.f, sd2 = 0.f, sgd = 0.f, amax = 0.f;
    for (int i = tid; i < RED_BLOCKS; i += 256) {
        float4 p = g_part[i];
        sg2 += p.x; sd2 += p.y; sgd += p.z; amax = fmaxf(amax, p.w);
    }
    #pragma unroll
    for (int off = 16; off; off >>= 1) {
        sg2 += __shfl_down_sync(0xffffffffu, sg2, off);
        sd2 += __shfl_down_sync(0xffffffffu, sd2, off);
        sgd += __shfl_down_sync(0xffffffffu, sgd, off);
        amax = fmaxf(amax, __shfl_down_sync(0xffffffffu, amax, off));
    }
    int lane = tid & 31, w = tid >> 5;
    if (!lane) sh[w] = make_float4(sg2, sd2, sgd, amax);
    __syncthreads();

    if (tid == 0) {
        float4 v = sh[0];
        #pragma unroll
        for (int i = 1; i < 8; i++) {
            float4 q = sh[i];
            v.x += q.x; v.y += q.y; v.z += q.z; v.w = fmaxf(v.w, q.w);
        }
        float gn = sqrtf(v.x);
        float dn = sqrtf(v.y);
        float inv_gn = (gn > 1e-10f) ? (1.0f / gn) : 1.0f;
        float inv_dn = (dn > 1e-10f) ? (1.0f / dn) : 1.0f;
        float it = (float)iter_p[0];
        sfeat[0] = log1pf(gn);
        sfeat[1] = log1pf(dn);
        sfeat[2] = v.z * inv_gn * inv_dn;
        sfeat[3] = v.w * inv_gn;
        sfeat[4] = it;
        sfeat[5] = logf(loss_cur[0]) - logf(loss_old[0]);
        g_inv_gn = inv_gn;
        g_inv_dn = inv_dn;
        g_fscale = 1.0f / sqrtf(1.0f + it);
    }
    __syncthreads();

    if (tid < 30) {
        float a = lb0[tid];
        #pragma unroll
        for (int f = 0; f < 6; f++) a = fmaf(lw0[tid * 6 + f], sfeat[f], a);
        sh0[tid] = fmaxf(a, 0.0f);
    }
    __syncthreads();
    if (tid < 20) {
        float a = lb1[tid];
        #pragma unroll
        for (int c = 0; c < 30; c++) a = fmaf(lw1[tid * 30 + c], sh0[c], a);
        sh1[tid] = fmaxf(a, 0.0f);
    }
    __syncthreads();
    if (tid < 10) {
        float a = lb2[tid];
        #pragma unroll
        for (int c = 0; c < 20; c++) a = fmaf(lw2[tid * 20 + c], sh1[c], a);
        sh2[tid] = fmaxf(a, 0.0f);
    }
    __syncthreads();
    if (tid < 4) {
        float a = lb3[tid];
        #pragma unroll
        for (int c = 0; c < 10; c++) a = fmaf(lw3[tid * 10 + c], sh2[c], a);
        g_coeff[tid] = a;
    }
}

// ---------------------------------------------------------------------------
// Kernel C: per-element 4->20->20->20->1 MLP, 1 element/thread, plain float.
// Named scalars only. Weights transposed in shared (row c = 20 outputs,
// 80 B row stride -> every float4 load is 16B-aligned, broadcast LDS).
// ---------------------------------------------------------------------------

// a0..a19 += w-row[C] * HV   : 5 aligned float4 broadcast loads + 20 FFMA
#define ACCROW(SW, C, HV) { \
    const float4* r_ = (const float4*)&(SW)[(C)][0]; \
    float4 q0 = r_[0], q1 = r_[1], q2 = r_[2], q3 = r_[3], q4 = r_[4]; \
    a0  = fmaf(q0.x, (HV), a0);  a1  = fmaf(q0.y, (HV), a1); \
    a2  = fmaf(q0.z, (HV), a2);  a3  = fmaf(q0.w, (HV), a3); \
    a4  = fmaf(q1.x, (HV), a4);  a5  = fmaf(q1.y, (HV), a5); \
    a6  = fmaf(q1.z, (HV), a6);  a7  = fmaf(q1.w, (HV), a7); \
    a8  = fmaf(q2.x, (HV), a8);  a9  = fmaf(q2.y, (HV), a9); \
    a10 = fmaf(q2.z, (HV), a10); a11 = fmaf(q2.w, (HV), a11); \
    a12 = fmaf(q3.x, (HV), a12); a13 = fmaf(q3.y, (HV), a13); \
    a14 = fmaf(q3.z, (HV), a14); a15 = fmaf(q3.w, (HV), a15); \
    a16 = fmaf(q4.x, (HV), a16); a17 = fmaf(q4.y, (HV), a17); \
    a18 = fmaf(q4.z, (HV), a18); a19 = fmaf(q4.w, (HV), a19); }

#define LOADB(SB) { \
    const float4* b_ = (const float4*)(SB); \
    float4 q0 = b_[0], q1 = b_[1], q2 = b_[2], q3 = b_[3], q4 = b_[4]; \
    a0 = q0.x;  a1 = q0.y;  a2 = q0.z;  a3 = q0.w; \
    a4 = q1.x;  a5 = q1.y;  a6 = q1.z;  a7 = q1.w; \
    a8 = q2.x;  a9 = q2.y;  a10 = q2.z; a11 = q2.w; \
    a12 = q3.x; a13 = q3.y; a14 = q3.z; a15 = q3.w; \
    a16 = q4.x; a17 = q4.y; a18 = q4.z; a19 = q4.w; }

#define RELUALL() \
    h0 = fmaxf(a0, 0.f);   h1 = fmaxf(a1, 0.f);   h2 = fmaxf(a2, 0.f); \
    h3 = fmaxf(a3, 0.f);   h4 = fmaxf(a4, 0.f);   h5 = fmaxf(a5, 0.f); \
    h6 = fmaxf(a6, 0.f);   h7 = fmaxf(a7, 0.f);   h8 = fmaxf(a8, 0.f); \
    h9 = fmaxf(a9, 0.f);   h10 = fmaxf(a10, 0.f); h11 = fmaxf(a11, 0.f); \
    h12 = fmaxf(a12, 0.f); h13 = fmaxf(a13, 0.f); h14 = fmaxf(a14, 0.f); \
    h15 = fmaxf(a15, 0.f); h16 = fmaxf(a16, 0.f); h17 = fmaxf(a17, 0.f); \
    h18 = fmaxf(a18, 0.f); h19 = fmaxf(a19, 0.f);

#define LAYER20(SW) \
    ACCROW(SW, 0, h0)   ACCROW(SW, 1, h1)   ACCROW(SW, 2, h2) \
    ACCROW(SW, 3, h3)   ACCROW(SW, 4, h4)   ACCROW(SW, 5, h5) \
    ACCROW(SW, 6, h6)   ACCROW(SW, 7, h7)   ACCROW(SW, 8, h8) \
    ACCROW(SW, 9, h9)   ACCROW(SW, 10, h10) ACCROW(SW, 11, h11) \
    ACCROW(SW, 12, h12) ACCROW(SW, 13, h13) ACCROW(SW, 14, h14) \
    ACCROW(SW, 15, h15) ACCROW(SW, 16, h16) ACCROW(SW, 17, h17) \
    ACCROW(SW, 18, h18) ACCROW(SW, 19, h19)

__global__ void __launch_bounds__(MAIN_THREADS) main_kernel(
    const float* __restrict__ grad, const float* __restrict__ s0,
    const float* __restrict__ s1, const float* __restrict__ gp,
    const float* __restrict__ ex,
    const float* __restrict__ cw0, const float* __restrict__ cb0,
    const float* __restrict__ cw1, const float* __restrict__ cb1,
    const float* __restrict__ cw2, const float* __restrict__ cb2,
    const float* __restrict__ cw3, const float* __restrict__ cb3,
    float* __restrict__ out, int n) {
    __shared__ __align__(16) float sw0[4][20];
    __shared__ __align__(16) float sw1[20][20];
    __shared__ __align__(16) float sw2[20][20];
    __shared__ __align__(16) float sw3[20];
    __shared__ __align__(16) float sb0[20];
    __shared__ __align__(16) float sb1[20];
    __shared__ __align__(16) float sb2[20];
    __shared__ float sb3f;

    int tid = threadIdx.x;

    float c0 = g_coeff[0], c1 = g_coeff[1], c2 = g_coeff[2], c3 = g_coeff[3];
    float inv_gn = g_inv_gn, inv_dn = g_inv_dn, fscale = g_fscale;

    // Stage weights, transposed (row = input channel). coeff folded into
    // layer-0 rows; fscale into layer-3 weights/bias.
    if (tid < 80) {
        int o = tid % 20, c = tid / 20;
        float cf = (c == 0) ? c0 : (c == 1) ? c1 : (c == 2) ? c2 : c3;
        sw0[c][o] = cw0[o * 4 + c] * cf;
    }
    for (int k = tid; k < 400; k += MAIN_THREADS) {
        int o = k % 20, c = k / 20;
        sw1[c][o] = cw1[o * 20 + c];
        sw2[c][o] = cw2[o * 20 + c];
    }
    if (tid < 20) {
        sw3[tid] = cw3[tid] * fscale;
        sb0[tid] = cb0[tid];
        sb1[tid] = cb1[tid];
        sb2[tid] = cb2[tid];
    }
    if (tid == 0) sb3f = cb3[0] * fscale;
    __syncthreads();

    int stride = gridDim.x * MAIN_THREADS;
    for (int i = blockIdx.x * MAIN_THREADS + tid; i < n; i += stride) {
        float gv = grad[i];
        float s0v = s0[i];
        float s1v = s1[i];
        float gpv = gp[i];
        float exv = ex[i];

        float gx = gv * inv_gn;
        float dx = (s1v - s0v) * inv_dn;
        float t0 = gpv * gx;   // gradient_param * g
        float t1 = exv * dx;   // extrapolation * d

        float a0, a1, a2, a3, a4, a5, a6, a7, a8, a9,
              a10, a11, a12, a13, a14, a15, a16, a17, a18, a19;
        float h0, h1, h2, h3, h4, h5, h6, h7, h8, h9,
              h10, h11, h12, h13, h14, h15, h16, h17, h18, h19;

        // ---- layer 0: 4 -> 20 ----
        LOADB(sb0)
        ACCROW(sw0, 0, t0)
        ACCROW(sw0, 1, t1)
        ACCROW(sw0, 2, gx)
        ACCROW(sw0, 3, dx)
        RELUALL()

        // ---- layer 1: 20 -> 20 ----
        LOADB(sb1)
        LAYER20(sw1)
        RELUALL()

        // ---- layer 2: 20 -> 20 ----
        LOADB(sb2)
        LAYER20(sw2)
        RELUALL()

        // ---- layer 3: 20 -> 1 (fscale folded) ----
        float acc = sb3f;
        {
            const float4* r_ = (const float4*)sw3;
            float4 q0 = r_[0], q1 = r_[1], q2 = r_[2], q3 = r_[3], q4 = r_[4];
            acc = fmaf(q0.x, h0, acc);   acc = fmaf(q0.y, h1, acc);
            acc = fmaf(q0.z, h2, acc);   acc = fmaf(q0.w, h3, acc);
            acc = fmaf(q1.x, h4, acc);   acc = fmaf(q1.y, h5, acc);
            acc = fmaf(q1.z, h6, acc);   acc = fmaf(q1.w, h7, acc);
            acc = fmaf(q2.x, h8, acc);   acc = fmaf(q2.y, h9, acc);
            acc = fmaf(q2.z, h10, acc);  acc = fmaf(q2.w, h11, acc);
            acc = fmaf(q3.x, h12, acc);  acc = fmaf(q3.y, h13, acc);
            acc = fmaf(q3.z, h14, acc);  acc = fmaf(q3.w, h15, acc);
            acc = fmaf(q4.x, h16, acc);  acc = fmaf(q4.y, h17, acc);
            acc = fmaf(q4.z, h18, acc);  acc = fmaf(q4.w, h19, acc);
        }
        out[i] = s1v + acc;
    }
}

// ---------------------------------------------------------------------------
extern "C" void kernel_launch(void* const* d_in, const int* in_sizes, int n_in,
                              void* d_out, int out_size) {
    const float* grad = (const float*)d_in[0];
    const float* s0   = (const float*)d_in[1];
    const float* s1   = (const float*)d_in[2];
    const float* loss_cur = (const float*)d_in[3];
    const float* loss_old = (const float*)d_in[4];
    const int*   iter_p   = (const int*)d_in[5];
    const float* gp = (const float*)d_in[6];
    const float* ex = (const float*)d_in[7];
    const float* cw0 = (const float*)d_in[8];
    const float* cb0 = (const float*)d_in[9];
    const float* cw1 = (const float*)d_in[10];
    const float* cb1 = (const float*)d_in[11];
    const float* cw2 = (const float*)d_in[12];
    const float* cb2 = (const float*)d_in[13];
    const float* cw3 = (const float*)d_in[14];
    const float* cb3 = (const float*)d_in[15];
    const float* lw0 = (const float*)d_in[16];
    const float* lb0 = (const float*)d_in[17];
    const float* lw1 = (const float*)d_in[18];
    const float* lb1 = (const float*)d_in[19];
    const float* lw2 = (const float*)d_in[20];
    const float* lb2 = (const float*)d_in[21];
    const float* lw3 = (const float*)d_in[22];
    const float* lb3 = (const float*)d_in[23];

    int n = in_sizes[0];

    reduce_kernel<<<RED_BLOCKS, RED_THREADS>>>(grad, s0, s1, n);
    scalars_kernel<<<1, 256>>>(loss_cur, loss_old, iter_p,
                               lw0, lb0, lw1, lb1, lw2, lb2, lw3, lb3);
    main_kernel<<<MAIN_BLOCKS, MAIN_THREADS>>>(grad, s0, s1, gp, ex,
                                               cw0, cb0, cw1, cb1, cw2, cb2,
                                               cw3, cb3, (float*)d_out, n);
}